// round 5
// baseline (speedup 1.0000x reference)
#include <cuda_runtime.h>
#include <cstddef>

// Problem constants
#define NN   50000
#define EE   800000
#define FF   512
#define HH   128
#define CC   40
#define TOTE (EE + NN)          // edges + self loops
#define SCAN_BS 512
#define SCAN_NB ((NN + SCAN_BS - 1) / SCAN_BS)   // 98

// ---------------- static scratch (device globals; no allocation) -------------
__device__ float g_deg[NN];
__device__ float g_dinv[NN];
__device__ int   g_cnt[NN];            // degree count, then reused as fill cursor
__device__ int   g_rowptr[NN + 1];
__device__ int   g_bsum[SCAN_NB];
__device__ int   g_boff[SCAN_NB];
__device__ int   g_csrc[TOTE];
__device__ float g_cnorm[TOTE];
__device__ float g_h [(size_t)NN * HH];
__device__ float g_hw[(size_t)NN * HH];
__device__ float g_t0[(size_t)NN * HH];
__device__ float g_t1[(size_t)NN * HH];
__device__ float g_concat[(size_t)NN * (5 * HH)];

// ---------------- graph preprocessing ---------------------------------------

__global__ void k_init() {
    int i = blockIdx.x * blockDim.x + threadIdx.x;
    if (i < NN) { g_deg[i] = 1.0f; g_cnt[i] = 1; }   // self loop: weight 1, count 1
}

__global__ void k_deg(const int* __restrict__ dst, const float* __restrict__ ew) {
    int e = blockIdx.x * blockDim.x + threadIdx.x;
    if (e < EE) {
        int d = dst[e];
        atomicAdd(&g_deg[d], ew[e]);
        atomicAdd(&g_cnt[d], 1);
    }
}

// block-local exclusive scan of g_cnt -> g_rowptr, block totals -> g_bsum
__global__ void k_scan1() {
    __shared__ int sh[SCAN_BS];
    int t = threadIdx.x;
    int idx = blockIdx.x * SCAN_BS + t;
    int v = (idx < NN) ? g_cnt[idx] : 0;
    sh[t] = v;
    __syncthreads();
    for (int off = 1; off < SCAN_BS; off <<= 1) {
        int x = (t >= off) ? sh[t - off] : 0;
        __syncthreads();
        sh[t] += x;
        __syncthreads();
    }
    if (idx < NN) g_rowptr[idx] = sh[t] - v;   // exclusive (block-local)
    if (t == SCAN_BS - 1) g_bsum[blockIdx.x] = sh[t];
}

__global__ void k_scan2() {
    if (threadIdx.x == 0 && blockIdx.x == 0) {
        int run = 0;
        for (int b = 0; b < SCAN_NB; b++) { int v = g_bsum[b]; g_boff[b] = run; run += v; }
    }
}

__global__ void k_scan3() {
    int t = threadIdx.x;
    int idx = blockIdx.x * SCAN_BS + t;
    if (idx < NN) g_rowptr[idx] += g_boff[blockIdx.x];
    if (idx == 0) g_rowptr[NN] = TOTE;
}

// dinv + deterministic self-loop entry at row start; reset cursor to 1
__global__ void k_dinv_self() {
    int n = blockIdx.x * blockDim.x + threadIdx.x;
    if (n < NN) {
        float di = rsqrtf(g_deg[n]);   // deg >= 1 always (self loop)
        g_dinv[n] = di;
        int p = g_rowptr[n];
        g_csrc[p]  = n;
        g_cnorm[p] = di * di;
        g_cnt[n]   = 1;                // cursor: self loop occupies slot 0
    }
}

__global__ void k_fill(const int* __restrict__ src, const int* __restrict__ dst,
                       const float* __restrict__ ew) {
    int e = blockIdx.x * blockDim.x + threadIdx.x;
    if (e < EE) {
        int s = src[e], d = dst[e];
        int off = atomicAdd(&g_cnt[d], 1);
        int p = g_rowptr[d] + off;
        g_csrc[p]  = s;
        g_cnorm[p] = g_dinv[s] * ew[e] * g_dinv[d];
    }
}

// ---------------- dense GEMMs (fp32 SIMT) ------------------------------------
// C[M,128] = A[M,K] @ B[K,128] (+bias); optional second destination C2.
// Tile: 64 rows x 128 cols per block, 256 threads, KT=16.
template<int K>
__global__ void __launch_bounds__(256) gemm_n128(
    const float* __restrict__ A, const float* __restrict__ B,
    const float* __restrict__ bias,
    float* __restrict__ C, int ldc,
    float* __restrict__ C2, int ldc2, int M)
{
    __shared__ float  As[16][65];
    __shared__ float4 Bs4[16 * 32];

    const int t = threadIdx.x;
    const int rg = t >> 5;       // 0..7  (row group)
    const int cg = t & 31;       // 0..31 (col group -> 4 cols)
    const int rowbase = blockIdx.x * 64;

    float4 acc[8];
#pragma unroll
    for (int i = 0; i < 8; i++) acc[i] = make_float4(0.f, 0.f, 0.f, 0.f);

    const int ar  = t >> 2;      // 0..63
    const int seg = t & 3;       // 0..3

    for (int kc = 0; kc < K; kc += 16) {
        // load A tile (transposed into smem)
        {
            int row = rowbase + ar;
            float4 av = make_float4(0.f, 0.f, 0.f, 0.f);
            if (row < M) av = *(const float4*)(A + (size_t)row * K + kc + seg * 4);
            As[seg * 4 + 0][ar] = av.x;
            As[seg * 4 + 1][ar] = av.y;
            As[seg * 4 + 2][ar] = av.z;
            As[seg * 4 + 3][ar] = av.w;
        }
        // load B tile
#pragma unroll
        for (int rep = 0; rep < 2; rep++) {
            int idx = t + rep * 256;
            int k = idx >> 5, c = idx & 31;
            Bs4[idx] = *(const float4*)(B + (size_t)(kc + k) * 128 + c * 4);
        }
        __syncthreads();

#pragma unroll
        for (int k = 0; k < 16; k++) {
            float4 b = Bs4[k * 32 + cg];
#pragma unroll
            for (int i = 0; i < 8; i++) {
                float a = As[k][rg * 8 + i];
                acc[i].x += a * b.x; acc[i].y += a * b.y;
                acc[i].z += a * b.z; acc[i].w += a * b.w;
            }
        }
        __syncthreads();
    }

    float4 bb = make_float4(0.f, 0.f, 0.f, 0.f);
    if (bias) bb = ((const float4*)bias)[cg];
#pragma unroll
    for (int i = 0; i < 8; i++) {
        int row = rowbase + rg * 8 + i;
        if (row < M) {
            float4 r = acc[i];
            r.x += bb.x; r.y += bb.y; r.z += bb.z; r.w += bb.w;
            ((float4*)(C + (size_t)row * ldc))[cg] = r;
            if (C2) ((float4*)(C2 + (size_t)row * ldc2))[cg] = r;
        }
    }
}

// Output GEMM: C[M,40] = A[M,640] @ B[640,40] + bias. Tile 128x40, 256 thr.
__global__ void __launch_bounds__(256) gemm_out(
    const float* __restrict__ A, const float* __restrict__ B,
    const float* __restrict__ bias, float* __restrict__ C, int M)
{
    __shared__ float As[16][129];
    __shared__ float Bs[16][41];

    const int t = threadIdx.x;
    const int rg = t >> 3;   // 0..31
    const int cg = t & 7;    // 0..7
    const int rowbase = blockIdx.x * 128;

    float acc[4][5];
#pragma unroll
    for (int i = 0; i < 4; i++)
#pragma unroll
        for (int j = 0; j < 5; j++) acc[i][j] = 0.f;

    for (int kc = 0; kc < 5 * HH; kc += 16) {
#pragma unroll
        for (int rep = 0; rep < 2; rep++) {
            int idx = t + rep * 256;
            int r = idx >> 2, seg = idx & 3;
            int row = rowbase + r;
            float4 av = make_float4(0.f, 0.f, 0.f, 0.f);
            if (row < M) av = *(const float4*)(A + (size_t)row * (5 * HH) + kc + seg * 4);
            As[seg * 4 + 0][r] = av.x;
            As[seg * 4 + 1][r] = av.y;
            As[seg * 4 + 2][r] = av.z;
            As[seg * 4 + 3][r] = av.w;
        }
        for (int i = t; i < 16 * CC; i += 256) {
            int k = i / CC, c = i % CC;
            Bs[k][c] = B[(size_t)(kc + k) * CC + c];
        }
        __syncthreads();

#pragma unroll
        for (int k = 0; k < 16; k++) {
            float a0 = As[k][rg], a1 = As[k][rg + 32], a2 = As[k][rg + 64], a3 = As[k][rg + 96];
#pragma unroll
            for (int j = 0; j < 5; j++) {
                float b = Bs[k][cg + 8 * j];
                acc[0][j] += a0 * b; acc[1][j] += a1 * b;
                acc[2][j] += a2 * b; acc[3][j] += a3 * b;
            }
        }
        __syncthreads();
    }

#pragma unroll
    for (int i = 0; i < 4; i++) {
        int row = rowbase + rg + 32 * i;
        if (row < M) {
#pragma unroll
            for (int j = 0; j < 5; j++) {
                int col = cg + 8 * j;
                C[(size_t)row * CC + col] = acc[i][j] + bias[col];
            }
        }
    }
}

// ---------------- sparse aggregation: out[n] = sum norm * hw[src] + b --------
// one warp per dst node; lane handles 4 contiguous features (float4)
__global__ void __launch_bounds__(256) agg_kernel(
    const float* __restrict__ hw, const float* __restrict__ bias,
    float* __restrict__ out, int ldout)
{
    int w = (blockIdx.x * blockDim.x + threadIdx.x) >> 5;
    int lane = threadIdx.x & 31;
    if (w >= NN) return;

    int beg = g_rowptr[w];
    int end = g_rowptr[w + 1];
    const float4* hw4 = (const float4*)hw;

    float4 acc = make_float4(0.f, 0.f, 0.f, 0.f);
    int i = beg;
    for (; i + 1 < end; i += 2) {
        int s0 = g_csrc[i], s1 = g_csrc[i + 1];
        float w0 = g_cnorm[i], w1 = g_cnorm[i + 1];
        float4 v0 = hw4[(size_t)s0 * 32 + lane];
        float4 v1 = hw4[(size_t)s1 * 32 + lane];
        acc.x += w0 * v0.x + w1 * v1.x;
        acc.y += w0 * v0.y + w1 * v1.y;
        acc.z += w0 * v0.z + w1 * v1.z;
        acc.w += w0 * v0.w + w1 * v1.w;
    }
    if (i < end) {
        int s = g_csrc[i];
        float wt = g_cnorm[i];
        float4 v = hw4[(size_t)s * 32 + lane];
        acc.x += wt * v.x; acc.y += wt * v.y; acc.z += wt * v.z; acc.w += wt * v.w;
    }
    float4 bb = ((const float4*)bias)[lane];
    acc.x += bb.x; acc.y += bb.y; acc.z += bb.z; acc.w += bb.w;
    *(float4*)(out + (size_t)w * ldout + lane * 4) = acc;
}

// ---------------- host driver ------------------------------------------------

extern "C" void kernel_launch(void* const* d_in, const int* in_sizes, int n_in,
                              void* d_out, int out_size)
{
    (void)in_sizes; (void)n_in; (void)out_size;

    const float* x     = (const float*)d_in[0];
    const int*   ei    = (const int*)d_in[1];   // [2, E]: src row, dst row
    const float* ew    = (const float*)d_in[2];
    const float* W_in  = (const float*)d_in[3];
    const float* b_in  = (const float*)d_in[4];
    const float* W_gcn = (const float*)d_in[5]; // [10,128,128]
    const float* b_gcn = (const float*)d_in[6]; // [10,128]
    const float* W_out = (const float*)d_in[7]; // [640,40]
    const float* b_out = (const float*)d_in[8];
    float* outp = (float*)d_out;

    const int* src = ei;
    const int* dst = ei + EE;

    float *p_h, *p_hw, *p_t0, *p_t1, *p_cc;
    cudaGetSymbolAddress((void**)&p_h,  g_h);
    cudaGetSymbolAddress((void**)&p_hw, g_hw);
    cudaGetSymbolAddress((void**)&p_t0, g_t0);
    cudaGetSymbolAddress((void**)&p_t1, g_t1);
    cudaGetSymbolAddress((void**)&p_cc, g_concat);

    // --- preprocessing: degrees, CSR build ---
    k_init<<<(NN + 255) / 256, 256>>>();
    k_deg<<<(EE + 255) / 256, 256>>>(dst, ew);
    k_scan1<<<SCAN_NB, SCAN_BS>>>();
    k_scan2<<<1, 32>>>();
    k_scan3<<<SCAN_NB, SCAN_BS>>>();
    k_dinv_self<<<(NN + 255) / 256, 256>>>();
    k_fill<<<(EE + 255) / 256, 256>>>(src, dst, ew);

    // --- input linear: h = x @ W_in + b_in; also write concat block 0 ---
    gemm_n128<FF><<<(NN + 63) / 64, 256>>>(x, W_in, b_in, p_h, HH, p_cc, 5 * HH, NN);

    // --- inception branches ---
    const int AGG_GRID = (NN * 32 + 255) / 256;   // one warp per node
    int k = 0;
    for (int j = 0; j < 4; j++) {
        const float* in = p_h;
        for (int s = 0; s <= j; s++) {
            gemm_n128<HH><<<(NN + 63) / 64, 256>>>(
                in, W_gcn + (size_t)k * HH * HH, nullptr, p_hw, HH, nullptr, 0, NN);
            bool last = (s == j);
            float* op = last ? (p_cc + (j + 1) * HH) : ((s & 1) ? p_t1 : p_t0);
            int ldo = last ? (5 * HH) : HH;
            agg_kernel<<<AGG_GRID, 256>>>(p_hw, b_gcn + (size_t)k * HH, op, ldo);
            in = op;
            k++;
        }
    }

    // --- output linear: out = concat @ W_out + b_out ---
    gemm_out<<<(NN + 127) / 128, 256>>>(p_cc, W_out, b_out, outp, NN);
}

// round 6
// speedup vs baseline: 1.5129x; 1.5129x over previous
#include <cuda_runtime.h>
#include <cstddef>

// Problem constants
#define NN   50000
#define EE   800000
#define FF   512
#define HH   128
#define CC   40
#define TOTE (EE + NN)          // edges + self loops
#define SCAN_BS 512
#define SCAN_NB ((NN + SCAN_BS - 1) / SCAN_BS)   // 98

// ---------------- static scratch (device globals; no allocation) -------------
__device__ float g_deg[NN];
__device__ float g_dinv[NN];
__device__ int   g_cnt[NN];
__device__ int   g_rowptr[NN + 1];
__device__ int   g_bsum[SCAN_NB];
__device__ int   g_boff[SCAN_NB];
__device__ int   g_csrc[TOTE];
__device__ float g_cnorm[TOTE];

__device__ float g_cc[(size_t)NN * 640];   // [h | Sh | S2h | S3h | S4h]
__device__ float g_r[NN];
__device__ float g_sr[NN];
__device__ float g_s2r[NN];

// small weight-chain products (128x128 each)
__device__ float g_P2[HH * HH];     // W1 W2
__device__ float g_Q34[HH * HH];    // W4 W5
__device__ float g_P3[HH * HH];     // W3 W4 W5
__device__ float g_Q89[HH * HH];    // W8 W9
__device__ float g_Q789[HH * HH];   // W7 W8 W9
__device__ float g_P4[HH * HH];     // W6 W7 W8 W9

__device__ float g_Acat[640 * CC];
__device__ float g_u_r[CC];
__device__ float g_u_sr[CC];
__device__ float g_u_s2r[CC];
__device__ float g_u_c[CC];

// ---------------- graph preprocessing ---------------------------------------

__global__ void k_init() {
    int i = blockIdx.x * blockDim.x + threadIdx.x;
    if (i < NN) { g_deg[i] = 1.0f; g_cnt[i] = 1; }   // self loop
}

__global__ void k_deg(const int* __restrict__ dst, const float* __restrict__ ew) {
    int e = blockIdx.x * blockDim.x + threadIdx.x;
    if (e < EE) {
        int d = dst[e];
        atomicAdd(&g_deg[d], ew[e]);
        atomicAdd(&g_cnt[d], 1);
    }
}

__global__ void k_scan1() {
    __shared__ int sh[SCAN_BS];
    int t = threadIdx.x;
    int idx = blockIdx.x * SCAN_BS + t;
    int v = (idx < NN) ? g_cnt[idx] : 0;
    sh[t] = v;
    __syncthreads();
    for (int off = 1; off < SCAN_BS; off <<= 1) {
        int x = (t >= off) ? sh[t - off] : 0;
        __syncthreads();
        sh[t] += x;
        __syncthreads();
    }
    if (idx < NN) g_rowptr[idx] = sh[t] - v;
    if (t == SCAN_BS - 1) g_bsum[blockIdx.x] = sh[t];
}

__global__ void k_scan2() {
    __shared__ int sh[128];
    int t = threadIdx.x;
    int v = (t < SCAN_NB) ? g_bsum[t] : 0;
    sh[t] = v;
    __syncthreads();
    for (int off = 1; off < 128; off <<= 1) {
        int x = (t >= off) ? sh[t - off] : 0;
        __syncthreads();
        sh[t] += x;
        __syncthreads();
    }
    if (t < SCAN_NB) g_boff[t] = sh[t] - v;   // exclusive
}

__global__ void k_scan3() {
    int t = threadIdx.x;
    int idx = blockIdx.x * SCAN_BS + t;
    if (idx < NN) g_rowptr[idx] += g_boff[blockIdx.x];
    if (idx == 0) g_rowptr[NN] = TOTE;
}

__global__ void k_dinv_self() {
    int n = blockIdx.x * blockDim.x + threadIdx.x;
    if (n < NN) {
        float di = rsqrtf(g_deg[n]);
        g_dinv[n] = di;
        int p = g_rowptr[n];
        g_csrc[p]  = n;
        g_cnorm[p] = di * di;
        g_cnt[n]   = 1;
    }
}

__global__ void k_fill(const int* __restrict__ src, const int* __restrict__ dst,
                       const float* __restrict__ ew) {
    int e = blockIdx.x * blockDim.x + threadIdx.x;
    if (e < EE) {
        int s = src[e], d = dst[e];
        int off = atomicAdd(&g_cnt[d], 1);
        int p = g_rowptr[d] + off;
        g_csrc[p]  = s;
        g_cnorm[p] = g_dinv[s] * ew[e] * g_dinv[d];
    }
}

// r-chain: vout[n] = sum_row cnorm * vin[src]   (vin==nullptr -> vin==1)
__global__ void __launch_bounds__(256) k_spmv_vec(const float* __restrict__ vin,
                                                  float* __restrict__ vout) {
    int w = (blockIdx.x * blockDim.x + threadIdx.x) >> 5;
    int lane = threadIdx.x & 31;
    if (w >= NN) return;
    int beg = g_rowptr[w], end = g_rowptr[w + 1];
    float a = 0.f;
    for (int i = beg + lane; i < end; i += 32)
        a += g_cnorm[i] * (vin ? vin[g_csrc[i]] : 1.0f);
    for (int o = 16; o; o >>= 1) a += __shfl_down_sync(0xffffffffu, a, o);
    if (lane == 0) vout[w] = a;
}

// ---------------- dense GEMM: C[M,128] = A[M,K] @ B[K,128] (+bias) -----------
// tile 128x128, 256 threads, 8x8 micro-tile
template<int K>
__global__ void __launch_bounds__(256) gemm_t128(
    const float* __restrict__ A, const float* __restrict__ B,
    const float* __restrict__ bias,
    float* __restrict__ C, int ldc, int M)
{
    __shared__ float  As[16][129];
    __shared__ float4 Bs4[16 * 32];

    const int t = threadIdx.x;
    const int ty = t >> 4;        // 0..15
    const int tx = t & 15;        // 0..15
    const int rowbase = blockIdx.x * 128;

    float4 acc[8][2];
#pragma unroll
    for (int i = 0; i < 8; i++) {
        acc[i][0] = make_float4(0.f, 0.f, 0.f, 0.f);
        acc[i][1] = make_float4(0.f, 0.f, 0.f, 0.f);
    }

    const int lr  = t >> 2;       // 0..63
    const int seg = t & 3;        // 0..3

    for (int kc = 0; kc < K; kc += 16) {
#pragma unroll
        for (int rep = 0; rep < 2; rep++) {
            int r = lr + rep * 64;
            int row = rowbase + r;
            float4 av = make_float4(0.f, 0.f, 0.f, 0.f);
            if (row < M) av = *(const float4*)(A + (size_t)row * K + kc + seg * 4);
            As[seg * 4 + 0][r] = av.x;
            As[seg * 4 + 1][r] = av.y;
            As[seg * 4 + 2][r] = av.z;
            As[seg * 4 + 3][r] = av.w;
        }
#pragma unroll
        for (int rep = 0; rep < 2; rep++) {
            int idx = t + rep * 256;
            int k = idx >> 5, c = idx & 31;
            Bs4[idx] = *(const float4*)(B + (size_t)(kc + k) * 128 + c * 4);
        }
        __syncthreads();

#pragma unroll
        for (int k = 0; k < 16; k++) {
            float4 b0 = Bs4[k * 32 + tx * 2];
            float4 b1 = Bs4[k * 32 + tx * 2 + 1];
#pragma unroll
            for (int i = 0; i < 8; i++) {
                float a = As[k][ty * 8 + i];
                acc[i][0].x += a * b0.x; acc[i][0].y += a * b0.y;
                acc[i][0].z += a * b0.z; acc[i][0].w += a * b0.w;
                acc[i][1].x += a * b1.x; acc[i][1].y += a * b1.y;
                acc[i][1].z += a * b1.z; acc[i][1].w += a * b1.w;
            }
        }
        __syncthreads();
    }

    float4 bb0 = make_float4(0.f, 0.f, 0.f, 0.f);
    float4 bb1 = make_float4(0.f, 0.f, 0.f, 0.f);
    if (bias) {
        bb0 = ((const float4*)bias)[tx * 2];
        bb1 = ((const float4*)bias)[tx * 2 + 1];
    }
#pragma unroll
    for (int i = 0; i < 8; i++) {
        int row = rowbase + ty * 8 + i;
        if (row < M) {
            float4 r0 = acc[i][0], r1 = acc[i][1];
            r0.x += bb0.x; r0.y += bb0.y; r0.z += bb0.z; r0.w += bb0.w;
            r1.x += bb1.x; r1.y += bb1.y; r1.z += bb1.z; r1.w += bb1.w;
            float4* cp = (float4*)(C + (size_t)row * ldc);
            cp[tx * 2]     = r0;
            cp[tx * 2 + 1] = r1;
        }
    }
}

// ---------------- sparse aggregation: out = S @ in (both stride 640) ---------
__global__ void __launch_bounds__(256) agg_kernel(
    const float* __restrict__ in, float* __restrict__ out)
{
    int w = (blockIdx.x * blockDim.x + threadIdx.x) >> 5;
    int lane = threadIdx.x & 31;
    if (w >= NN) return;

    int beg = g_rowptr[w];
    int end = g_rowptr[w + 1];
    const float4* in4 = (const float4*)in;

    float4 acc = make_float4(0.f, 0.f, 0.f, 0.f);
    int i = beg;
    for (; i + 1 < end; i += 2) {
        int s0 = g_csrc[i], s1 = g_csrc[i + 1];
        float w0 = g_cnorm[i], w1 = g_cnorm[i + 1];
        float4 v0 = in4[(size_t)s0 * 160 + lane];
        float4 v1 = in4[(size_t)s1 * 160 + lane];
        acc.x += w0 * v0.x + w1 * v1.x;
        acc.y += w0 * v0.y + w1 * v1.y;
        acc.z += w0 * v0.z + w1 * v1.z;
        acc.w += w0 * v0.w + w1 * v1.w;
    }
    if (i < end) {
        int s = g_csrc[i];
        float wt = g_cnorm[i];
        float4 v = in4[(size_t)s * 160 + lane];
        acc.x += wt * v.x; acc.y += wt * v.y;
        acc.z += wt * v.z; acc.w += wt * v.w;
    }
    *(float4*)(out + (size_t)w * 640 + lane * 4) = acc;
}

// ---------------- Acat blocks: Acat[j] = M_j @ Wout_j  (j=0 copy) ------------
__global__ void __launch_bounds__(256) k_buildA(const float* __restrict__ W0,
                                                const float* __restrict__ W_out)
{
    int j = blockIdx.x;
    int t = threadIdx.x;
    float* dstp = g_Acat + (size_t)j * HH * CC;
    const float* Wj = W_out + (size_t)j * HH * CC;

    if (j == 0) {
        for (int i = t; i < HH * CC; i += 256) dstp[i] = Wj[i];
        return;
    }
    const float* M = (j == 1) ? W0 : (j == 2) ? g_P2 : (j == 3) ? g_P3 : g_P4;

    __shared__ float Bs[HH * CC];
    for (int i = t; i < HH * CC; i += 256) Bs[i] = Wj[i];
    __syncthreads();

    int row = t >> 1;
    int cb  = (t & 1) * 20;
    float acc[20];
#pragma unroll
    for (int c = 0; c < 20; c++) acc[c] = 0.f;
    for (int k = 0; k < HH; k++) {
        float a = M[row * HH + k];
#pragma unroll
        for (int c = 0; c < 20; c++) acc[c] += a * Bs[k * CC + cb + c];
    }
#pragma unroll
    for (int c = 0; c < 20; c++) dstp[row * CC + cb + c] = acc[c];
}

// ---------------- fold all GCN biases into u vectors -------------------------
__global__ void k_bias_fold(const float* __restrict__ W_gcn,
                            const float* __restrict__ b_gcn,
                            const float* __restrict__ W_out,
                            const float* __restrict__ b_out)
{
    __shared__ float w[HH];
    __shared__ float ur[CC], usr[CC], us2r[CC];
    int t = threadIdx.x;   // 128 threads
    if (t < CC) { ur[t] = 0.f; usr[t] = 0.f; us2r[t] = 0.f; }
    __syncthreads();

    auto term = [&](const float* b, const float* M, int jout, float* tgt) {
        float s = 0.f;
        for (int k = 0; k < HH; k++) s += b[k] * M[k * HH + t];
        w[t] = s;
        __syncthreads();
        if (t < CC) {
            const float* Wj = W_out + (size_t)jout * HH * CC;
            float s2 = 0.f;
            for (int k = 0; k < HH; k++) s2 += w[k] * Wj[k * CC + t];
            tgt[t] += s2;
        }
        __syncthreads();
    };

    term(b_gcn + 1 * HH, W_gcn + (size_t)2 * HH * HH, 2, ur);   // (b1 W2) Wout2
    term(b_gcn + 4 * HH, W_gcn + (size_t)5 * HH * HH, 3, ur);   // (b4 W5) Wout3
    term(b_gcn + 8 * HH, W_gcn + (size_t)9 * HH * HH, 4, ur);   // (b8 W9) Wout4
    term(b_gcn + 3 * HH, g_Q34,  3, usr);                       // (b3 W4W5) Wout3
    term(b_gcn + 7 * HH, g_Q89,  4, usr);                       // (b7 W8W9) Wout4
    term(b_gcn + 6 * HH, g_Q789, 4, us2r);                      // (b6 W7W8W9) Wout4

    if (t < CC) {
        float s = b_out[t];
        for (int k = 0; k < HH; k++) {
            s += b_gcn[0 * HH + k] * W_out[(size_t)(1 * HH + k) * CC + t];
            s += b_gcn[2 * HH + k] * W_out[(size_t)(2 * HH + k) * CC + t];
            s += b_gcn[5 * HH + k] * W_out[(size_t)(3 * HH + k) * CC + t];
            s += b_gcn[9 * HH + k] * W_out[(size_t)(4 * HH + k) * CC + t];
        }
        g_u_c[t]   = s;
        g_u_r[t]   = ur[t];
        g_u_sr[t]  = usr[t];
        g_u_s2r[t] = us2r[t];
    }
}

// ---------------- output GEMM with rank-1 fold epilogue ----------------------
// out[M,40] = cc[M,640] @ Acat[640,40] + u_c + r*u_r + sr*u_sr + s2r*u_s2r
__global__ void __launch_bounds__(256) gemm_out_fold(
    const float* __restrict__ A, float* __restrict__ C, int M)
{
    __shared__ float As[16][129];
    __shared__ float Bs[16][41];
    __shared__ float su_r[CC], su_sr[CC], su_s2r[CC], su_c[CC];

    const int t = threadIdx.x;
    if (t < CC) {
        su_r[t] = g_u_r[t]; su_sr[t] = g_u_sr[t];
        su_s2r[t] = g_u_s2r[t]; su_c[t] = g_u_c[t];
    }

    const int rg = t >> 3;   // 0..31
    const int cg = t & 7;    // 0..7
    const int rowbase = blockIdx.x * 128;

    float acc[4][5];
#pragma unroll
    for (int i = 0; i < 4; i++)
#pragma unroll
        for (int j = 0; j < 5; j++) acc[i][j] = 0.f;

    for (int kc = 0; kc < 5 * HH; kc += 16) {
#pragma unroll
        for (int rep = 0; rep < 2; rep++) {
            int idx = t + rep * 256;
            int r = idx >> 2, seg = idx & 3;
            int row = rowbase + r;
            float4 av = make_float4(0.f, 0.f, 0.f, 0.f);
            if (row < M) av = *(const float4*)(A + (size_t)row * (5 * HH) + kc + seg * 4);
            As[seg * 4 + 0][r] = av.x;
            As[seg * 4 + 1][r] = av.y;
            As[seg * 4 + 2][r] = av.z;
            As[seg * 4 + 3][r] = av.w;
        }
        for (int i = t; i < 16 * CC; i += 256) {
            int k = i / CC, c = i % CC;
            Bs[k][c] = g_Acat[(size_t)(kc + k) * CC + c];
        }
        __syncthreads();

#pragma unroll
        for (int k = 0; k < 16; k++) {
            float a0 = As[k][rg], a1 = As[k][rg + 32], a2 = As[k][rg + 64], a3 = As[k][rg + 96];
#pragma unroll
            for (int j = 0; j < 5; j++) {
                float b = Bs[k][cg + 8 * j];
                acc[0][j] += a0 * b; acc[1][j] += a1 * b;
                acc[2][j] += a2 * b; acc[3][j] += a3 * b;
            }
        }
        __syncthreads();
    }

#pragma unroll
    for (int i = 0; i < 4; i++) {
        int row = rowbase + rg + 32 * i;
        if (row < M) {
            float rv = g_r[row], srv = g_sr[row], s2rv = g_s2r[row];
#pragma unroll
            for (int j = 0; j < 5; j++) {
                int col = cg + 8 * j;
                C[(size_t)row * CC + col] = acc[i][j] + su_c[col]
                    + rv * su_r[col] + srv * su_sr[col] + s2rv * su_s2r[col];
            }
        }
    }
}

// ---------------- host driver ------------------------------------------------

extern "C" void kernel_launch(void* const* d_in, const int* in_sizes, int n_in,
                              void* d_out, int out_size)
{
    (void)in_sizes; (void)n_in; (void)out_size;

    const float* x     = (const float*)d_in[0];
    const int*   ei    = (const int*)d_in[1];
    const float* ew    = (const float*)d_in[2];
    const float* W_in  = (const float*)d_in[3];
    const float* b_in  = (const float*)d_in[4];
    const float* W_gcn = (const float*)d_in[5];  // [10,128,128]
    const float* b_gcn = (const float*)d_in[6];  // [10,128]
    const float* W_out = (const float*)d_in[7];  // [640,40]
    const float* b_out = (const float*)d_in[8];
    float* outp = (float*)d_out;

    const int* src = ei;
    const int* dst = ei + EE;

    float *p_cc, *p_r, *p_sr, *p_s2r;
    float *p_P2, *p_Q34, *p_P3, *p_Q89, *p_Q789, *p_P4;
    cudaGetSymbolAddress((void**)&p_cc,   g_cc);
    cudaGetSymbolAddress((void**)&p_r,    g_r);
    cudaGetSymbolAddress((void**)&p_sr,   g_sr);
    cudaGetSymbolAddress((void**)&p_s2r,  g_s2r);
    cudaGetSymbolAddress((void**)&p_P2,   g_P2);
    cudaGetSymbolAddress((void**)&p_Q34,  g_Q34);
    cudaGetSymbolAddress((void**)&p_P3,   g_P3);
    cudaGetSymbolAddress((void**)&p_Q89,  g_Q89);
    cudaGetSymbolAddress((void**)&p_Q789, g_Q789);
    cudaGetSymbolAddress((void**)&p_P4,   g_P4);

    // --- CSR build ---
    k_init<<<(NN + 255) / 256, 256>>>();
    k_deg<<<(EE + 255) / 256, 256>>>(dst, ew);
    k_scan1<<<SCAN_NB, SCAN_BS>>>();
    k_scan2<<<1, 128>>>();
    k_scan3<<<SCAN_NB, SCAN_BS>>>();
    k_dinv_self<<<(NN + 255) / 256, 256>>>();
    k_fill<<<(EE + 255) / 256, 256>>>(src, dst, ew);

    // --- r chain: r = S 1, sr = S r, s2r = S sr ---
    const int VEC_GRID = (NN * 32 + 255) / 256;
    k_spmv_vec<<<VEC_GRID, 256>>>(nullptr, p_r);
    k_spmv_vec<<<VEC_GRID, 256>>>(p_r, p_sr);
    k_spmv_vec<<<VEC_GRID, 256>>>(p_sr, p_s2r);

    // --- small weight-chain products (128x128 each, 1 block) ---
    const float* W1 = W_gcn + (size_t)1 * HH * HH;
    const float* W2 = W_gcn + (size_t)2 * HH * HH;
    const float* W3 = W_gcn + (size_t)3 * HH * HH;
    const float* W4 = W_gcn + (size_t)4 * HH * HH;
    const float* W5 = W_gcn + (size_t)5 * HH * HH;
    const float* W6 = W_gcn + (size_t)6 * HH * HH;
    const float* W7 = W_gcn + (size_t)7 * HH * HH;
    const float* W8 = W_gcn + (size_t)8 * HH * HH;
    const float* W9 = W_gcn + (size_t)9 * HH * HH;
    gemm_t128<HH><<<1, 256>>>(W1, W2, nullptr, p_P2, HH, HH);
    gemm_t128<HH><<<1, 256>>>(W4, W5, nullptr, p_Q34, HH, HH);
    gemm_t128<HH><<<1, 256>>>(W8, W9, nullptr, p_Q89, HH, HH);
    gemm_t128<HH><<<1, 256>>>(W3, p_Q34, nullptr, p_P3, HH, HH);
    gemm_t128<HH><<<1, 256>>>(W7, p_Q89, nullptr, p_Q789, HH, HH);
    gemm_t128<HH><<<1, 256>>>(W6, p_Q789, nullptr, p_P4, HH, HH);

    // --- Acat blocks + bias folds ---
    k_buildA<<<5, 256>>>(W_gcn /* W0 */, W_out);
    k_bias_fold<<<1, 128>>>(W_gcn, b_gcn, W_out, b_out);

    // --- h = x @ W_in + b_in -> cc block 0 ---
    gemm_t128<FF><<<(NN + 127) / 128, 256>>>(x, W_in, b_in, p_cc, 640, NN);

    // --- q chain: q_{i+1} = S q_i, stored in cc blocks 1..4 ---
    for (int i = 0; i < 4; i++)
        agg_kernel<<<VEC_GRID, 256>>>(p_cc + i * HH, p_cc + (i + 1) * HH);

    // --- out = cc @ Acat + rank-1 folds ---
    gemm_out_fold<<<(NN + 127) / 128, 256>>>(p_cc, outp, NN);
}

// round 7
// speedup vs baseline: 2.3066x; 1.5246x over previous
#include <cuda_runtime.h>
#include <cstddef>

// Problem constants
#define NN   50000
#define EE   800000
#define FF   512
#define HH   128
#define CC   40
#define TOTE (EE + NN)          // edges + self loops
#define SCAN_BS 512
#define SCAN_NB ((NN + SCAN_BS - 1) / SCAN_BS)   // 98

// ---------------- static scratch (device globals; no allocation) -------------
__device__ float g_deg[NN];
__device__ float g_dinv[NN];
__device__ int   g_cnt[NN];
__device__ int   g_rowptr[NN + 1];
__device__ int   g_bsum[SCAN_NB];
__device__ int   g_boff[SCAN_NB];
__device__ int   g_csrc[TOTE];
__device__ float g_cnorm[TOTE];

__device__ float g_cc[(size_t)NN * 640];   // [h | Sh | S2h | S3h | S4h]
__device__ float g_r[NN];
__device__ float g_sr[NN];
__device__ float g_s2r[NN];

__device__ float g_Acat[5 * HH * CC];      // 5 blocks of 128x40
__device__ float g_uc[CC];
__device__ float g_ur_p[3 * CC];           // contributions from branches 2,3,4
__device__ float g_usr_p[2 * CC];          // from branches 3,4
__device__ float g_us2r[CC];               // from branch 4

// ---------------- graph preprocessing ---------------------------------------

__global__ void k_init() {
    int i = blockIdx.x * blockDim.x + threadIdx.x;
    if (i < NN) { g_deg[i] = 1.0f; g_cnt[i] = 1; }   // self loop
}

__global__ void k_deg(const int* __restrict__ dst, const float* __restrict__ ew) {
    int e = blockIdx.x * blockDim.x + threadIdx.x;
    if (e < EE) {
        int d = dst[e];
        atomicAdd(&g_deg[d], ew[e]);
        atomicAdd(&g_cnt[d], 1);
    }
}

__global__ void k_scan1() {
    __shared__ int sh[SCAN_BS];
    int t = threadIdx.x;
    int idx = blockIdx.x * SCAN_BS + t;
    int v = (idx < NN) ? g_cnt[idx] : 0;
    sh[t] = v;
    __syncthreads();
    for (int off = 1; off < SCAN_BS; off <<= 1) {
        int x = (t >= off) ? sh[t - off] : 0;
        __syncthreads();
        sh[t] += x;
        __syncthreads();
    }
    if (idx < NN) g_rowptr[idx] = sh[t] - v;
    if (t == SCAN_BS - 1) g_bsum[blockIdx.x] = sh[t];
}

__global__ void k_scan2() {
    __shared__ int sh[128];
    int t = threadIdx.x;
    int v = (t < SCAN_NB) ? g_bsum[t] : 0;
    sh[t] = v;
    __syncthreads();
    for (int off = 1; off < 128; off <<= 1) {
        int x = (t >= off) ? sh[t - off] : 0;
        __syncthreads();
        sh[t] += x;
        __syncthreads();
    }
    if (t < SCAN_NB) g_boff[t] = sh[t] - v;   // exclusive
}

__global__ void k_scan3() {
    int t = threadIdx.x;
    int idx = blockIdx.x * SCAN_BS + t;
    if (idx < NN) g_rowptr[idx] += g_boff[blockIdx.x];
    if (idx == 0) g_rowptr[NN] = TOTE;
}

__global__ void k_dinv_self() {
    int n = blockIdx.x * blockDim.x + threadIdx.x;
    if (n < NN) {
        float di = rsqrtf(g_deg[n]);
        g_dinv[n] = di;
        int p = g_rowptr[n];
        g_csrc[p]  = n;
        g_cnorm[p] = di * di;
        g_cnt[n]   = 1;
    }
}

__global__ void k_fill(const int* __restrict__ src, const int* __restrict__ dst,
                       const float* __restrict__ ew) {
    int e = blockIdx.x * blockDim.x + threadIdx.x;
    if (e < EE) {
        int s = src[e], d = dst[e];
        int off = atomicAdd(&g_cnt[d], 1);
        int p = g_rowptr[d] + off;
        g_csrc[p]  = s;
        g_cnorm[p] = g_dinv[s] * ew[e] * g_dinv[d];
    }
}

// r-chain: vout[n] = sum_row cnorm * vin[src]   (vin==nullptr -> vin==1)
__global__ void __launch_bounds__(256) k_spmv_vec(const float* __restrict__ vin,
                                                  float* __restrict__ vout) {
    int w = (blockIdx.x * blockDim.x + threadIdx.x) >> 5;
    int lane = threadIdx.x & 31;
    if (w >= NN) return;
    int beg = g_rowptr[w], end = g_rowptr[w + 1];
    float a = 0.f;
    for (int i = beg + lane; i < end; i += 32)
        a += g_cnorm[i] * (vin ? vin[g_csrc[i]] : 1.0f);
    for (int o = 16; o; o >>= 1) a += __shfl_down_sync(0xffffffffu, a, o);
    if (lane == 0) vout[w] = a;
}

// ---------------- dense GEMM: C[M,128] = A[M,K] @ B[K,128] (+bias) -----------
// tile 128x128, 256 threads, 8x8 micro-tile
template<int K>
__global__ void __launch_bounds__(256) gemm_t128(
    const float* __restrict__ A, const float* __restrict__ B,
    const float* __restrict__ bias,
    float* __restrict__ C, int ldc, int M)
{
    __shared__ float  As[16][129];
    __shared__ float4 Bs4[16 * 32];

    const int t = threadIdx.x;
    const int ty = t >> 4;        // 0..15
    const int tx = t & 15;        // 0..15
    const int rowbase = blockIdx.x * 128;

    float4 acc[8][2];
#pragma unroll
    for (int i = 0; i < 8; i++) {
        acc[i][0] = make_float4(0.f, 0.f, 0.f, 0.f);
        acc[i][1] = make_float4(0.f, 0.f, 0.f, 0.f);
    }

    const int lr  = t >> 2;       // 0..63
    const int seg = t & 3;        // 0..3

    for (int kc = 0; kc < K; kc += 16) {
#pragma unroll
        for (int rep = 0; rep < 2; rep++) {
            int r = lr + rep * 64;
            int row = rowbase + r;
            float4 av = make_float4(0.f, 0.f, 0.f, 0.f);
            if (row < M) av = *(const float4*)(A + (size_t)row * K + kc + seg * 4);
            As[seg * 4 + 0][r] = av.x;
            As[seg * 4 + 1][r] = av.y;
            As[seg * 4 + 2][r] = av.z;
            As[seg * 4 + 3][r] = av.w;
        }
#pragma unroll
        for (int rep = 0; rep < 2; rep++) {
            int idx = t + rep * 256;
            int k = idx >> 5, c = idx & 31;
            Bs4[idx] = *(const float4*)(B + (size_t)(kc + k) * 128 + c * 4);
        }
        __syncthreads();

#pragma unroll
        for (int k = 0; k < 16; k++) {
            float4 b0 = Bs4[k * 32 + tx * 2];
            float4 b1 = Bs4[k * 32 + tx * 2 + 1];
#pragma unroll
            for (int i = 0; i < 8; i++) {
                float a = As[k][ty * 8 + i];
                acc[i][0].x += a * b0.x; acc[i][0].y += a * b0.y;
                acc[i][0].z += a * b0.z; acc[i][0].w += a * b0.w;
                acc[i][1].x += a * b1.x; acc[i][1].y += a * b1.y;
                acc[i][1].z += a * b1.z; acc[i][1].w += a * b1.w;
            }
        }
        __syncthreads();
    }

    float4 bb0 = make_float4(0.f, 0.f, 0.f, 0.f);
    float4 bb1 = make_float4(0.f, 0.f, 0.f, 0.f);
    if (bias) {
        bb0 = ((const float4*)bias)[tx * 2];
        bb1 = ((const float4*)bias)[tx * 2 + 1];
    }
#pragma unroll
    for (int i = 0; i < 8; i++) {
        int row = rowbase + ty * 8 + i;
        if (row < M) {
            float4 r0 = acc[i][0], r1 = acc[i][1];
            r0.x += bb0.x; r0.y += bb0.y; r0.z += bb0.z; r0.w += bb0.w;
            r1.x += bb1.x; r1.y += bb1.y; r1.z += bb1.z; r1.w += bb1.w;
            float4* cp = (float4*)(C + (size_t)row * ldc);
            cp[tx * 2]     = r0;
            cp[tx * 2 + 1] = r1;
        }
    }
}

// ---------------- sparse aggregation: out = S @ in (both stride 640) ---------
__global__ void __launch_bounds__(256) agg_kernel(
    const float* __restrict__ in, float* __restrict__ out)
{
    int w = (blockIdx.x * blockDim.x + threadIdx.x) >> 5;
    int lane = threadIdx.x & 31;
    if (w >= NN) return;

    int beg = g_rowptr[w];
    int end = g_rowptr[w + 1];
    const float4* in4 = (const float4*)in;

    float4 acc = make_float4(0.f, 0.f, 0.f, 0.f);
    int i = beg;
    for (; i + 1 < end; i += 2) {
        int s0 = g_csrc[i], s1 = g_csrc[i + 1];
        float w0 = g_cnorm[i], w1 = g_cnorm[i + 1];
        float4 v0 = in4[(size_t)s0 * 160 + lane];
        float4 v1 = in4[(size_t)s1 * 160 + lane];
        acc.x += w0 * v0.x + w1 * v1.x;
        acc.y += w0 * v0.y + w1 * v1.y;
        acc.z += w0 * v0.z + w1 * v1.z;
        acc.w += w0 * v0.w + w1 * v1.w;
    }
    if (i < end) {
        int s = g_csrc[i];
        float wt = g_cnorm[i];
        float4 v = in4[(size_t)s * 160 + lane];
        acc.x += wt * v.x; acc.y += wt * v.y;
        acc.z += wt * v.z; acc.w += wt * v.w;
    }
    *(float4*)(out + (size_t)w * 640 + lane * 4) = acc;
}

// ---------------- right-to-left weight chains --------------------------------
// Per branch b (block b): chain W products applied to Wout_b (128x40),
// tapping bias contributions from intermediates. Block 0: A0 copy + u_c.
__global__ void __launch_bounds__(256) k_chains(
    const float* __restrict__ W_gcn, const float* __restrict__ b_gcn,
    const float* __restrict__ W_out, const float* __restrict__ b_out)
{
    __shared__ float tA[HH * CC];
    __shared__ float tB[HH * CC];
    const int b = blockIdx.x;
    const int t = threadIdx.x;

    if (b == 0) {
        for (int i = t; i < HH * CC; i += 256) g_Acat[i] = W_out[i];
        if (t < CC) {
            float s = b_out[t];
            for (int k = 0; k < HH; k++) {
                s += b_gcn[0 * HH + k] * W_out[(size_t)(1 * HH + k) * CC + t];
                s += b_gcn[2 * HH + k] * W_out[(size_t)(2 * HH + k) * CC + t];
                s += b_gcn[5 * HH + k] * W_out[(size_t)(3 * HH + k) * CC + t];
                s += b_gcn[9 * HH + k] * W_out[(size_t)(4 * HH + k) * CC + t];
            }
            g_uc[t] = s;
        }
        return;
    }

    // load Wout block b
    for (int i = t; i < HH * CC; i += 256) tA[i] = W_out[(size_t)b * HH * CC + i];
    __syncthreads();

    float* cur = tA;
    float* nxt = tB;
    const int start = (b - 1) * b / 2;   // first W index of branch b-1 (0-based)

    const int row = t >> 1;     // 0..127
    const int half = t & 1;     // 0..1 -> 20 cols each

    for (int p = 1; p <= b; p++) {
        const float* Wr = W_gcn + (size_t)(start + b - p) * HH * HH + (size_t)row * HH;
        float acc[20];
#pragma unroll
        for (int c = 0; c < 20; c++) acc[c] = 0.f;
        for (int k = 0; k < HH; k++) {
            float a = Wr[k];
            const float* srcp = cur + k * CC + half * 20;
#pragma unroll
            for (int c = 0; c < 20; c++) acc[c] += a * srcp[c];
        }
        float* dstp = nxt + row * CC + half * 20;
#pragma unroll
        for (int c = 0; c < 20; c++) dstp[c] = acc[c];
        __syncthreads();

        if (p < b && t < CC) {   // bias tap on the intermediate
            const float* bb = b_gcn + (size_t)(start + b - p - 1) * HH;
            float s = 0.f;
            for (int k = 0; k < HH; k++) s += bb[k] * nxt[k * CC + t];
            if (p == 1)      g_ur_p[(b - 2) * CC + t] = s;
            else if (p == 2) g_usr_p[(b - 3) * CC + t] = s;
            else             g_us2r[t] = s;
        }
        float* tmp = cur; cur = nxt; nxt = tmp;
    }

    for (int i = t; i < HH * CC; i += 256)
        g_Acat[(size_t)b * HH * CC + i] = cur[i];
}

// ---------------- partial output GEMM: C (+)= q[M,128] @ Aj[128,40] ----------
// INIT also adds u_c + r*u_r + sr*u_sr + s2r*u_s2r.
template<bool INIT>
__global__ void __launch_bounds__(256) k_pout(
    const float* __restrict__ q, const float* __restrict__ Aj,
    float* __restrict__ C, int M)
{
    __shared__ float Bsf[HH * CC];
    __shared__ float As[16][129];
    __shared__ float su_c[CC], su_r[CC], su_sr[CC], su_s2r[CC];

    const int t = threadIdx.x;
    for (int i = t; i < HH * CC; i += 256) Bsf[i] = Aj[i];
    if (INIT && t < CC) {
        su_c[t]   = g_uc[t];
        su_r[t]   = g_ur_p[t] + g_ur_p[CC + t] + g_ur_p[2 * CC + t];
        su_sr[t]  = g_usr_p[t] + g_usr_p[CC + t];
        su_s2r[t] = g_us2r[t];
    }

    const int rg = t >> 3;   // 0..31
    const int cg = t & 7;    // 0..7
    const int rowbase = blockIdx.x * 128;

    float acc[4][5];
#pragma unroll
    for (int i = 0; i < 4; i++)
#pragma unroll
        for (int j = 0; j < 5; j++) acc[i][j] = 0.f;

    for (int kc = 0; kc < HH; kc += 16) {
#pragma unroll
        for (int rep = 0; rep < 2; rep++) {
            int idx = t + rep * 256;
            int r = idx >> 2, seg = idx & 3;
            int row = rowbase + r;
            float4 av = make_float4(0.f, 0.f, 0.f, 0.f);
            if (row < M) av = *(const float4*)(q + (size_t)row * 640 + kc + seg * 4);
            As[seg * 4 + 0][r] = av.x;
            As[seg * 4 + 1][r] = av.y;
            As[seg * 4 + 2][r] = av.z;
            As[seg * 4 + 3][r] = av.w;
        }
        __syncthreads();

#pragma unroll
        for (int k = 0; k < 16; k++) {
            float a0 = As[k][rg], a1 = As[k][rg + 32], a2 = As[k][rg + 64], a3 = As[k][rg + 96];
#pragma unroll
            for (int j = 0; j < 5; j++) {
                float bv = Bsf[(kc + k) * CC + cg + 8 * j];
                acc[0][j] += a0 * bv; acc[1][j] += a1 * bv;
                acc[2][j] += a2 * bv; acc[3][j] += a3 * bv;
            }
        }
        __syncthreads();
    }

#pragma unroll
    for (int i = 0; i < 4; i++) {
        int row = rowbase + rg + 32 * i;
        if (row < M) {
            if (INIT) {
                float rv = g_r[row], srv = g_sr[row], s2rv = g_s2r[row];
#pragma unroll
                for (int j = 0; j < 5; j++) {
                    int col = cg + 8 * j;
                    C[(size_t)row * CC + col] = acc[i][j] + su_c[col]
                        + rv * su_r[col] + srv * su_sr[col] + s2rv * su_s2r[col];
                }
            } else {
#pragma unroll
                for (int j = 0; j < 5; j++) {
                    int col = cg + 8 * j;
                    C[(size_t)row * CC + col] += acc[i][j];
                }
            }
        }
    }
}

// ---------------- stream/event setup at static-init (outside checkpoints) ----
struct StreamInit {
    bool ok = false;
    int dev = -1;
    cudaStream_t sB{}, sC{};
    cudaEvent_t ev[9]{};
    StreamInit() {
        ok = (cudaStreamCreateWithFlags(&sB, cudaStreamNonBlocking) == cudaSuccess) &&
             (cudaStreamCreateWithFlags(&sC, cudaStreamNonBlocking) == cudaSuccess);
        for (int i = 0; i < 9 && ok; i++)
            ok = (cudaEventCreateWithFlags(&ev[i], cudaEventDisableTiming) == cudaSuccess);
        if (ok) cudaGetDevice(&dev);
    }
};
static StreamInit g_si;

// ---------------- host driver ------------------------------------------------

extern "C" void kernel_launch(void* const* d_in, const int* in_sizes, int n_in,
                              void* d_out, int out_size)
{
    (void)in_sizes; (void)n_in; (void)out_size;

    const float* x     = (const float*)d_in[0];
    const int*   ei    = (const int*)d_in[1];
    const float* ew    = (const float*)d_in[2];
    const float* W_in  = (const float*)d_in[3];
    const float* b_in  = (const float*)d_in[4];
    const float* W_gcn = (const float*)d_in[5];  // [10,128,128]
    const float* b_gcn = (const float*)d_in[6];  // [10,128]
    const float* W_out = (const float*)d_in[7];  // [640,40]
    const float* b_out = (const float*)d_in[8];
    float* outp = (float*)d_out;

    const int* src = ei;
    const int* dst = ei + EE;

    float *p_cc, *p_r, *p_sr, *p_s2r, *p_acat;
    cudaGetSymbolAddress((void**)&p_cc,   g_cc);
    cudaGetSymbolAddress((void**)&p_r,    g_r);
    cudaGetSymbolAddress((void**)&p_sr,   g_sr);
    cudaGetSymbolAddress((void**)&p_s2r,  g_s2r);
    cudaGetSymbolAddress((void**)&p_acat, g_Acat);

    int curdev = -1;
    cudaGetDevice(&curdev);
    const bool par = g_si.ok && (curdev == g_si.dev);
    cudaStream_t s0 = 0;
    cudaStream_t sB = par ? g_si.sB : (cudaStream_t)0;
    cudaStream_t sC = par ? g_si.sC : (cudaStream_t)0;
    cudaEvent_t e0   = g_si.ev[0], eB = g_si.ev[1], eC = g_si.ev[2], eR = g_si.ev[3];
    cudaEvent_t eA0  = g_si.ev[4], eA1 = g_si.ev[5], eA2 = g_si.ev[6], eA3 = g_si.ev[7];
    cudaEvent_t eF   = g_si.ev[8];

    // fork
    if (par) {
        cudaEventRecord(e0, s0);
        cudaStreamWaitEvent(sB, e0, 0);
        cudaStreamWaitEvent(sC, e0, 0);
    }

    // sB: input linear h = x @ W_in + b_in -> cc block 0
    gemm_t128<FF><<<(NN + 127) / 128, 256, 0, sB>>>(x, W_in, b_in, p_cc, 640, NN);
    if (par) cudaEventRecord(eB, sB);

    // sC: weight chains (Acat + bias folds)
    k_chains<<<5, 256, 0, sC>>>(W_gcn, b_gcn, W_out, b_out);
    if (par) cudaEventRecord(eC, sC);

    // s0: CSR build
    k_init<<<(NN + 255) / 256, 256, 0, s0>>>();
    k_deg<<<(EE + 255) / 256, 256, 0, s0>>>(dst, ew);
    k_scan1<<<SCAN_NB, SCAN_BS, 0, s0>>>();
    k_scan2<<<1, 128, 0, s0>>>();
    k_scan3<<<SCAN_NB, SCAN_BS, 0, s0>>>();
    k_dinv_self<<<(NN + 255) / 256, 256, 0, s0>>>();
    k_fill<<<(EE + 255) / 256, 256, 0, s0>>>(src, dst, ew);

    // s0: r chain
    const int VEC_GRID = (NN * 32 + 255) / 256;
    k_spmv_vec<<<VEC_GRID, 256, 0, s0>>>(nullptr, p_r);
    k_spmv_vec<<<VEC_GRID, 256, 0, s0>>>(p_r, p_sr);
    k_spmv_vec<<<VEC_GRID, 256, 0, s0>>>(p_sr, p_s2r);
    if (par) cudaEventRecord(eR, s0);

    // s0: aggregation chain (needs h from sB)
    if (par) cudaStreamWaitEvent(s0, eB, 0);
    agg_kernel<<<VEC_GRID, 256, 0, s0>>>(p_cc + 0 * HH, p_cc + 1 * HH);
    if (par) cudaEventRecord(eA0, s0);
    agg_kernel<<<VEC_GRID, 256, 0, s0>>>(p_cc + 1 * HH, p_cc + 2 * HH);
    if (par) cudaEventRecord(eA1, s0);
    agg_kernel<<<VEC_GRID, 256, 0, s0>>>(p_cc + 2 * HH, p_cc + 3 * HH);
    if (par) cudaEventRecord(eA2, s0);
    agg_kernel<<<VEC_GRID, 256, 0, s0>>>(p_cc + 3 * HH, p_cc + 4 * HH);
    if (par) cudaEventRecord(eA3, s0);

    // sB: partial output GEMMs, each as its q block becomes ready
    const int PG = (NN + 127) / 128;
    if (par) { cudaStreamWaitEvent(sB, eC, 0); cudaStreamWaitEvent(sB, eR, 0); }
    k_pout<true><<<PG, 256, 0, sB>>>(p_cc + 0 * HH, p_acat + 0 * HH * CC, outp, NN);
    if (par) cudaStreamWaitEvent(sB, eA0, 0);
    k_pout<false><<<PG, 256, 0, sB>>>(p_cc + 1 * HH, p_acat + 1 * HH * CC, outp, NN);
    if (par) cudaStreamWaitEvent(sB, eA1, 0);
    k_pout<false><<<PG, 256, 0, sB>>>(p_cc + 2 * HH, p_acat + 2 * HH * CC, outp, NN);
    if (par) cudaStreamWaitEvent(sB, eA2, 0);
    k_pout<false><<<PG, 256, 0, sB>>>(p_cc + 3 * HH, p_acat + 3 * HH * CC, outp, NN);
    if (par) cudaStreamWaitEvent(sB, eA3, 0);
    k_pout<false><<<PG, 256, 0, sB>>>(p_cc + 4 * HH, p_acat + 4 * HH * CC, outp, NN);

    // join back to capture stream
    if (par) {
        cudaEventRecord(eF, sB);
        cudaStreamWaitEvent(s0, eF, 0);
    }
}